// round 12
// baseline (speedup 1.0000x reference)
#include <cuda_runtime.h>
#include <cstddef>

// x: (8, 16, 3, 256, 256) fp32; out: (128, 2, 256, 256) fp32
// out[bl, ch, hw] = plane(bl*3) - plane((bl-1)*3), zero when bl%16==0; ch0==ch1.
//
// Final-family config: fully coalesced, 1 float4/thread, __ldg loads +
// __stcs streaming stores. Block geometry is the only lever that has
// measured positive (256->512 helped); this round: 1024-thread blocks.

static constexpr int HW4 = 16384;         // 256*256/4
static constexpr int BL  = 128;           // 8*16
static constexpr int TOTAL4 = BL * HW4;   // 2,097,152 float4 threads

__global__ __launch_bounds__(1024) void dummyflow_diff_kernel(
    const float4* __restrict__ x, float4* __restrict__ out)
{
    int idx = blockIdx.x * blockDim.x + threadIdx.x;

    int bl = idx >> 14;         // idx / HW4
    int hw = idx & (HW4 - 1);   // idx % HW4
    int l  = bl & 15;

    float4 v;
    if (l == 0) {
        v = make_float4(0.f, 0.f, 0.f, 0.f);
    } else {
        size_t cur  = (size_t)(bl * 3)       * HW4 + hw;
        size_t prev = (size_t)((bl - 1) * 3) * HW4 + hw;
        float4 a = __ldg(&x[cur]);
        float4 p = __ldg(&x[prev]);
        v = make_float4(a.x - p.x, a.y - p.y, a.z - p.z, a.w - p.w);
    }

    size_t o = (size_t)(bl * 2) * HW4 + hw;
    __stcs(&out[o], v);         // channel 0 — streaming (evict-first)
    __stcs(&out[o + HW4], v);   // channel 1
}

extern "C" void kernel_launch(void* const* d_in, const int* in_sizes, int n_in,
                              void* d_out, int out_size)
{
    const float4* x = (const float4*)d_in[0];
    float4* out = (float4*)d_out;

    int threads = 1024;
    int blocks = TOTAL4 / threads;   // 2048, exact
    dummyflow_diff_kernel<<<blocks, threads>>>(x, out);
}

// round 13
// speedup vs baseline: 1.1311x; 1.1311x over previous
#include <cuda_runtime.h>
#include <cstddef>

// x: (8, 16, 3, 256, 256) fp32; out: (128, 2, 256, 256) fp32
// out[bl, ch, hw] = plane(bl*3) - plane((bl-1)*3), zero when bl%16==0; ch0==ch1.
//
// FINAL (R10 optimum): fully coalesced, 1 float4/thread, __ldg loads +
// __stcs streaming stores, 512-thread blocks. Measured best of all families:
//   cache policy: default / stwt / stcs / evict_last  -> stcs best
//   vector width: 128b / 256b                         -> equal, 128b best wall
//   ILP: 1 / 2 / 4 / 16-chain                         -> flat
//   block: 256 / 512 / 1024                           -> 512 best
// Kernel sits at the ~6.8 TB/s effective mixed-R/W HBM roofline for its
// 100 MB compulsory traffic (33.5 MB reads + 67 MB writes).

static constexpr int HW4 = 16384;         // 256*256/4
static constexpr int BL  = 128;           // 8*16
static constexpr int TOTAL4 = BL * HW4;   // 2,097,152 float4 threads

__global__ __launch_bounds__(512) void dummyflow_diff_kernel(
    const float4* __restrict__ x, float4* __restrict__ out)
{
    int idx = blockIdx.x * blockDim.x + threadIdx.x;
    if (idx >= TOTAL4) return;

    int bl = idx >> 14;         // idx / HW4
    int hw = idx & (HW4 - 1);   // idx % HW4
    int l  = bl & 15;

    float4 v;
    if (l == 0) {
        v = make_float4(0.f, 0.f, 0.f, 0.f);
    } else {
        size_t cur  = (size_t)(bl * 3)       * HW4 + hw;
        size_t prev = (size_t)((bl - 1) * 3) * HW4 + hw;
        float4 a = __ldg(&x[cur]);
        float4 p = __ldg(&x[prev]);
        v = make_float4(a.x - p.x, a.y - p.y, a.z - p.z, a.w - p.w);
    }

    size_t o = (size_t)(bl * 2) * HW4 + hw;
    __stcs(&out[o], v);         // channel 0 — streaming (evict-first)
    __stcs(&out[o + HW4], v);   // channel 1
}

extern "C" void kernel_launch(void* const* d_in, const int* in_sizes, int n_in,
                              void* d_out, int out_size)
{
    const float4* x = (const float4*)d_in[0];
    float4* out = (float4*)d_out;

    int threads = 512;
    int blocks = (TOTAL4 + threads - 1) / threads;  // 4096
    dummyflow_diff_kernel<<<blocks, threads>>>(x, out);
}

// round 14
// speedup vs baseline: 1.1383x; 1.0064x over previous
#include <cuda_runtime.h>
#include <cstddef>

// x: (8, 16, 3, 256, 256) fp32; out: (128, 2, 256, 256) fp32
// out[bl, ch, hw] = plane(bl*3) - plane((bl-1)*3), zero when bl%16==0; ch0==ch1.
//
// FINAL: fully coalesced, 1 float4/thread, __ldg loads + __stcs streaming
// stores, 512-thread blocks, exact grid (no bounds check). Swept and settled:
//   cache policy: default / stwt / stcs / evict_last  -> stcs best
//   vector width: 128b / 256b                         -> 128b best wall
//   ILP: 1 / 2 / 4 / 16-chain                         -> flat
//   block: 256 / 512 / 1024                           -> 512 best
// Pinned at ~6.6-6.8 TB/s effective mixed-R/W HBM throughput for the
// 100 MB compulsory traffic (33.5 MB reads + 67 MB writes).

static constexpr int HW4 = 16384;         // 256*256/4
static constexpr int BL  = 128;           // 8*16
static constexpr int TOTAL4 = BL * HW4;   // 2,097,152 float4 threads (= 4096*512)

__global__ __launch_bounds__(512) void dummyflow_diff_kernel(
    const float4* __restrict__ x, float4* __restrict__ out)
{
    int idx = blockIdx.x * blockDim.x + threadIdx.x;   // grid exact: no guard

    int bl = idx >> 14;         // idx / HW4
    int hw = idx & (HW4 - 1);   // idx % HW4
    int l  = bl & 15;

    float4 v;
    if (l == 0) {
        v = make_float4(0.f, 0.f, 0.f, 0.f);
    } else {
        size_t cur  = (size_t)(bl * 3)       * HW4 + hw;
        size_t prev = (size_t)((bl - 1) * 3) * HW4 + hw;
        float4 a = __ldg(&x[cur]);
        float4 p = __ldg(&x[prev]);
        v = make_float4(a.x - p.x, a.y - p.y, a.z - p.z, a.w - p.w);
    }

    size_t o = (size_t)(bl * 2) * HW4 + hw;
    __stcs(&out[o], v);         // channel 0 — streaming (evict-first)
    __stcs(&out[o + HW4], v);   // channel 1
}

extern "C" void kernel_launch(void* const* d_in, const int* in_sizes, int n_in,
                              void* d_out, int out_size)
{
    const float4* x = (const float4*)d_in[0];
    float4* out = (float4*)d_out;

    dummyflow_diff_kernel<<<TOTAL4 / 512, 512>>>(x, out);   // 4096 blocks, exact
}